// round 15
// baseline (speedup 1.0000x reference)
#include <cuda_runtime.h>

// MaskRCNN RPN split v4:
//  K1 (1023 blocks): streaming scores/boxes/anchors + labels=0, ILP-2.
//  K2 (40 blocks, one per (batch,gt)): sweep 15 (level,atype) units, scatter
//      positive labels over conservative rects. Serial order => race-free.

#define B_   2
#define A_   20
#define NTOT 261888

#define OUT_SC 0
#define OUT_BX (B_ * NTOT * 2)
#define OUT_AN (OUT_BX + B_ * NTOT * 4)
#define OUT_LB (OUT_AN + B_ * NTOT * 4)

struct LvlPtrs {
    const float* cs[5];
    const float* bp[5];
};

__constant__ int c_offv[5] = {0, 196608, 245760, 258048, 261120};

__global__ void __launch_bounds__(256)
rpn_stream_kernel(LvlPtrs p, float* __restrict__ out)
{
    int t = blockIdx.x * blockDim.x + threadIdx.x;
    int gid = t * 2;
    if (gid >= B_ * NTOT) return;

    int b = (gid >= NTOT) ? 1 : 0;
    int n = gid - b * NTOT;

    int lvl, offv;
    if      (n < 196608) { lvl = 0; offv = 0;      }
    else if (n < 245760) { lvl = 1; offv = 196608; }
    else if (n < 258048) { lvl = 2; offv = 245760; }
    else if (n < 261120) { lvl = 3; offv = 258048; }
    else                 { lvl = 4; offv = 261120; }

    int log2w  = 8 - lvl;
    int log2hw = 2 * log2w;
    int hw     = 1 << log2hw;

    int local = n - offv;
    int a   = local >> log2hw;
    int rem = local & (hw - 1);
    int y   = rem >> log2w;
    int x0  = rem & ((1 << log2w) - 1);

    float s    = (float)(1 << (lvl + 2));
    float half = 0.5f * (s - 1.0f);
    float base = (float)(1 << (lvl + 6));
    float cy  = s * (float)y + half;
    float cx0 = s * (float)x0 + half;
    float hh = (a == 2) ? 2.0f * base : base;
    float ww = (a == 0) ? 2.0f * base : base;

    const float* csp = p.cs[lvl];
    const float* bpp = p.bp[lvl];
    int cbase = (b * 6  + a * 2) * hw + rem;
    int bbase = (b * 12 + a * 4) * hw + rem;

    float2 c0 = *reinterpret_cast<const float2*>(csp + cbase);
    float2 c1 = *reinterpret_cast<const float2*>(csp + cbase + hw);
    float2 dy = *reinterpret_cast<const float2*>(bpp + bbase);
    float2 dx = *reinterpret_cast<const float2*>(bpp + bbase + hw);
    float2 dh = *reinterpret_cast<const float2*>(bpp + bbase + 2 * hw);
    float2 dw = *reinterpret_cast<const float2*>(bpp + bbase + 3 * hw);

    int row = b * NTOT + n;

    *reinterpret_cast<float4*>(out + OUT_SC + row * 2) =
        make_float4(c0.x, c1.x, c0.y, c1.y);

    float dyv[2] = {dy.x, dy.y};
    float dxv[2] = {dx.x, dx.y};
    float dhv[2] = {dh.x, dh.y};
    float dwv[2] = {dw.x, dw.y};

    float4* bx = reinterpret_cast<float4*>(out + OUT_BX + row * 4);
    float4* an = reinterpret_cast<float4*>(out + OUT_AN + row * 4);

#pragma unroll
    for (int j = 0; j < 2; ++j) {
        float cxj = cx0 + (float)j * s;
        float cyc = cy  + dyv[j] * hh;
        float cxc = cxj + dxv[j] * ww;
        float h2  = hh * __expf(dhv[j]);
        float w2  = ww * __expf(dwv[j]);
        bx[j] = make_float4(cyc - 0.5f * h2, cxc - 0.5f * w2,
                            cyc + 0.5f * h2, cxc + 0.5f * w2);
        an[j] = make_float4(cy, cxj, hh, ww);
    }

    *reinterpret_cast<float2*>(out + OUT_LB + row) = make_float2(0.0f, 0.0f);
}

__global__ void __launch_bounds__(256)
rpn_label_scatter(const float* __restrict__ gt,
                  const int* __restrict__ gtc,
                  float* __restrict__ out)
{
    int blk = blockIdx.x;                    // 40 blocks: one per (b, g)
    int b = blk / A_;
    int g = blk - b * A_;
    int tx = threadIdx.x;

    int cnt = gtc[b];
    cnt = (cnt < 0) ? 0 : (cnt > A_ ? A_ : cnt);
    if (g >= cnt) return;

    float4 gb = reinterpret_cast<const float4*>(gt)[b * A_ + g];
    float gh = __fsub_rn(gb.z, gb.x);
    float gw = __fsub_rn(gb.w, gb.y);
    float ga = __fmul_rn(gh, gw);

#pragma unroll
    for (int lvl = 0; lvl < 5; ++lvl) {
        int log2w = 8 - lvl;
        int w  = 1 << log2w;
        int hw = w * w;
        float s    = (float)(1 << (lvl + 2));
        float half = 0.5f * (s - 1.0f);
        float base = (float)(1 << (lvl + 6));

#pragma unroll
        for (int a = 0; a < 3; ++a) {
            float hh = (a == 2) ? 2.0f * base : base;
            float ww = (a == 0) ? 2.0f * base : base;
            float area = __fmul_rn(hh, ww);
            float thr  = __fadd_rn(area, ga);
            float req  = thr * (1.0f / 3.0f) * 0.9999f;
            if (fminf(area, ga) < req) continue;   // size-incompatible

            float hh2 = 0.5f * hh, ww2 = 0.5f * ww;
            float oy_max = fminf(hh, gh);
            float ox_max = fminf(ww, gw);
            float oy_req = (req / ox_max) * 0.9999f;
            float ox_req = (req / oy_max) * 0.9999f;

            int ylo = (int)floorf((gb.x + oy_req - hh2 - half) / s) - 1;
            int yhi = (int)ceilf ((gb.z - oy_req + hh2 - half) / s) + 1;
            int xlo = (int)floorf((gb.y + ox_req - ww2 - half) / s) - 1;
            int xhi = (int)ceilf ((gb.w - ox_req + ww2 - half) / s) + 1;
            ylo = max(ylo, 0); yhi = min(yhi, w - 1);
            xlo = max(xlo, 0); xhi = min(xhi, w - 1);
            if (ylo > yhi || xlo > xhi) continue;

            int nx = xhi - xlo + 1;
            int ncand = (yhi - ylo + 1) * nx;

            float kthr = thr * (1.0f / 3.0f);
            float m_hi = kthr * 1.00002f;
            float m_lo = kthr * 0.99998f;
            int abase = OUT_LB + b * NTOT + c_offv[lvl] + (a << (2 * log2w));

            for (int idx = tx; idx < ncand; idx += 256) {
                int yy = idx / nx;
                int xx = idx - yy * nx;
                int y = ylo + yy;
                int x = xlo + xx;

                float cy  = s * (float)y + half;
                float cx  = s * (float)x + half;
                float ay1 = __fsub_rn(cy, hh2);
                float ay2 = __fadd_rn(ay1, hh);
                float ax1 = __fsub_rn(cx, ww2);
                float ax2 = __fadd_rn(ax1, ww);

                float yy1 = fminf(fmaxf(ay1, gb.x), gb.z);
                float yy2 = fminf(fmaxf(ay2, gb.x), gb.z);
                float xx1 = fminf(fmaxf(ax1, gb.y), gb.w);
                float xx2 = fminf(fmaxf(ax2, gb.y), gb.w);
                float inter = __fmul_rn(__fsub_rn(yy2, yy1), __fsub_rn(xx2, xx1));

                bool pos = false;
                if (inter >= m_hi)      pos = true;
                else if (inter >= m_lo) {
                    // ambiguous band: the reference's own fp32 division
                    float uni = __fsub_rn(thr, inter);
                    pos = (inter / uni >= 0.5f);
                }
                if (pos) out[abase + (y << log2w) + x] = 1.0f;
            }
        }
    }
}

extern "C" void kernel_launch(void* const* d_in, const int* in_sizes, int n_in,
                              void* d_out, int out_size)
{
    LvlPtrs p;
    const float* gt = nullptr;
    const int* gtc = nullptr;
    const int cs_sz[5] = {786432, 196608, 49152, 12288, 3072};
    const int bp_sz[5] = {1572864, 393216, 98304, 24576, 6144};

    for (int k = 0; k < n_in; ++k) {
        int sz = in_sizes[k];
        bool matched = false;
        for (int l = 0; l < 5 && !matched; ++l) {
            if (sz == cs_sz[l]) { p.cs[l] = (const float*)d_in[k]; matched = true; }
            else if (sz == bp_sz[l]) { p.bp[l] = (const float*)d_in[k]; matched = true; }
        }
        if (!matched) {
            if (sz == B_ * A_ * 4) gt = (const float*)d_in[k];
            else if (sz == B_)     gtc = (const int*)d_in[k];
        }
    }

    float* out = (float*)d_out;
    int threads = 256;
    int total_t = (B_ * NTOT) / 2;                  // 261888
    int blocks = (total_t + threads - 1) / threads; // 1023
    rpn_stream_kernel<<<blocks, threads>>>(p, out);

    rpn_label_scatter<<<B_ * A_, 256>>>(gt, gtc, out);   // 40 blocks
}

// round 16
// speedup vs baseline: 1.8174x; 1.8174x over previous
#include <cuda_runtime.h>

// MaskRCNN RPN monolithic v6: single kernel, 1023 blocks (one wave), ILP-2.
// Stream part identical to the best-measured R6 path; labels computed inline
// over block-culled GT survivors (size-compat + block y-overlap, smem).
// Boundary blocks (batch/level crossing) take a full-GT fallback loop.

#define B_   2
#define A_   20
#define NTOT 261888

#define OUT_SC 0
#define OUT_BX (B_ * NTOT * 2)
#define OUT_AN (OUT_BX + B_ * NTOT * 4)
#define OUT_LB (OUT_AN + B_ * NTOT * 4)

struct LvlPtrs {
    const float* cs[5];
    const float* bp[5];
};

__device__ __forceinline__ void get_level(int n, int& lvl, int& offv) {
    if      (n < 196608) { lvl = 0; offv = 0;      }
    else if (n < 245760) { lvl = 1; offv = 196608; }
    else if (n < 258048) { lvl = 2; offv = 245760; }
    else if (n < 261120) { lvl = 3; offv = 258048; }
    else                 { lvl = 4; offv = 261120; }
}

__global__ void __launch_bounds__(256, 8)
rpn_kernel(LvlPtrs p,
           const float* __restrict__ gt,   // B*A*4
           const int* __restrict__ gtc,    // B (int32 as delivered)
           float* __restrict__ out)
{
    __shared__ float4 s_gb[A_];
    __shared__ float  s_sga[A_];
    __shared__ int    s_ns;
    __shared__ int    s_cnt[B_];

    int tx = threadIdx.x;

    // ---- block uniformity (batch & level constant across the block's 512 anchors?)
    int gid0 = blockIdx.x * 512;
    int gidL = gid0 + 511;
    int bb0 = (gid0 >= NTOT) ? 1 : 0;
    int bbL = (gidL >= NTOT) ? 1 : 0;
    int lvl0, off0, lvlL, offL;
    get_level(gid0 - bb0 * NTOT, lvl0, off0);
    get_level(gidL - bbL * NTOT, lvlL, offL);
    bool uniform = (bb0 == bbL) && (lvl0 == lvlL);

    // ---- per-thread indices + geometry
    int gid = gid0 + tx * 2;
    int b = (gid >= NTOT) ? 1 : 0;
    int n = gid - b * NTOT;
    int lvl, offv;
    get_level(n, lvl, offv);

    int log2w  = 8 - lvl;
    int log2hw = 2 * log2w;
    int hw     = 1 << log2hw;

    int local = n - offv;
    int a   = local >> log2hw;
    int rem = local & (hw - 1);
    int y   = rem >> log2w;
    int x0  = rem & ((1 << log2w) - 1);

    float s    = (float)(1 << (lvl + 2));
    float half = 0.5f * (s - 1.0f);
    float base = (float)(1 << (lvl + 6));
    float cy  = s * (float)y + half;
    float cx0 = s * (float)x0 + half;
    float hh = (a == 2) ? 2.0f * base : base;
    float ww = (a == 0) ? 2.0f * base : base;

    const float* csp = p.cs[lvl];
    const float* bpp = p.bp[lvl];
    int cbase = (b * 6  + a * 2) * hw + rem;
    int bbase = (b * 12 + a * 4) * hw + rem;

    float2 c0 = *reinterpret_cast<const float2*>(csp + cbase);
    float2 c1 = *reinterpret_cast<const float2*>(csp + cbase + hw);
    float2 dy = *reinterpret_cast<const float2*>(bpp + bbase);
    float2 dx = *reinterpret_cast<const float2*>(bpp + bbase + hw);
    float2 dh = *reinterpret_cast<const float2*>(bpp + bbase + 2 * hw);
    float2 dw = *reinterpret_cast<const float2*>(bpp + bbase + 3 * hw);

    // ---- GT culling into shared (uses block-leader geometry)
    if (tx < B_) {
        int c = gtc[tx];
        s_cnt[tx] = (c < 0) ? 0 : (c > A_ ? A_ : c);
    }
    if (tx == 0) s_ns = 0;
    __syncthreads();

    if (uniform && tx < A_) {
        float s0    = (float)(1 << (lvl0 + 2));
        float half0 = 0.5f * (s0 - 1.0f);
        float base0 = (float)(1 << (lvl0 + 6));
        float area1 = base0 * base0;
        int log2w0  = 8 - lvl0;
        int log2hw0 = 2 * log2w0;
        int hw0     = 1 << log2hw0;
        int w0      = 1 << log2w0;

        int la0 = gid0 - bb0 * NTOT - off0;
        int laL = la0 + 511;
        int a0c = la0 >> log2hw0;
        int a1c = laL >> log2hw0;
        int yblo, ybhi;
        if (a0c != a1c) { yblo = 0; ybhi = w0 - 1; }
        else {
            yblo = (la0 & (hw0 - 1)) >> log2w0;
            ybhi = (laL & (hw0 - 1)) >> log2w0;
        }

        if (tx < s_cnt[bb0]) {
            float4 gb = reinterpret_cast<const float4*>(gt)[bb0 * A_ + tx];
            float gh = __fsub_rn(gb.z, gb.x);
            float gw = __fsub_rn(gb.w, gb.y);
            float ga = __fmul_rn(gh, gw);
            bool okA = 3.0f * fminf(area1, ga)        >= 0.999f * (area1 + ga);
            bool okB = 3.0f * fminf(2.0f * area1, ga) >= 0.999f * (2.0f * area1 + ga);
            bool survive = okA || okB;
            if (survive) {
                float lo = gb.x - base0 - half0;     // hh_max/2 = base0
                float hi = gb.z + base0 - half0;
                int gylo = (int)floorf(lo / s0) - 1;
                int gyhi = (int)ceilf (hi / s0) + 1;
                if (gyhi < yblo || gylo > ybhi) survive = false;
            }
            if (survive) {
                int slot = atomicAdd(&s_ns, 1);
                s_gb[slot]  = gb;
                s_sga[slot] = ga;
            }
        }
    }
    __syncthreads();

    // ---- stream outputs
    int row = b * NTOT + n;

    *reinterpret_cast<float4*>(out + OUT_SC + row * 2) =
        make_float4(c0.x, c1.x, c0.y, c1.y);

    float dyv[2] = {dy.x, dy.y};
    float dxv[2] = {dx.x, dx.y};
    float dhv[2] = {dh.x, dh.y};
    float dwv[2] = {dw.x, dw.y};

    float4* bx = reinterpret_cast<float4*>(out + OUT_BX + row * 4);
    float4* an = reinterpret_cast<float4*>(out + OUT_AN + row * 4);

#pragma unroll
    for (int j = 0; j < 2; ++j) {
        float cxj = cx0 + (float)j * s;
        float cyc = cy  + dyv[j] * hh;
        float cxc = cxj + dxv[j] * ww;
        float h2  = hh * __expf(dhv[j]);
        float w2  = ww * __expf(dwv[j]);
        bx[j] = make_float4(cyc - 0.5f * h2, cxc - 0.5f * w2,
                            cyc + 0.5f * h2, cxc + 0.5f * w2);
        an[j] = make_float4(cy, cxj, hh, ww);
    }

    // ---- labels (survivor loop; fallback = full loop for boundary blocks)
    float ay1 = cy - 0.5f * hh;
    float ay2 = ay1 + hh;
    float ax1_0 = cx0 - 0.5f * ww;
    float area = __fmul_rn(hh, ww);
    float oxm_w = ww;                       // per-GT oxmax = min(ww, gw)

    unsigned labm = 0;
    if (uniform) {
        int ns = s_ns;
        for (int k = 0; k < ns; ++k) {
            float4 gb = s_gb[k];
            float ga  = s_sga[k];
            float thr = __fadd_rn(area, ga);
            float kthr = thr * (1.0f / 3.0f);

            float yy1 = fminf(fmaxf(ay1, gb.x), gb.z);
            float yy2 = fminf(fmaxf(ay2, gb.x), gb.z);
            float oy  = __fsub_rn(yy2, yy1);
            float oxmax = fminf(oxm_w, __fsub_rn(gb.w, gb.y));
            if (__fmul_rn(oy, oxmax) < kthr * 0.999f) continue;

            float m_hi = kthr * 1.00002f;
            float m_lo = kthr * 0.99998f;
#pragma unroll
            for (int j = 0; j < 2; ++j) {
                float a1 = ax1_0 + (float)j * s;
                float a2 = a1 + ww;
                float xx1 = fminf(fmaxf(a1, gb.y), gb.w);
                float xx2 = fminf(fmaxf(a2, gb.y), gb.w);
                float inter = __fmul_rn(oy, __fsub_rn(xx2, xx1));
                if (inter >= m_lo) {
                    if (inter >= m_hi) labm |= (1u << j);
                    else {
                        float uni = __fsub_rn(thr, inter);
                        if (inter / uni >= 0.5f) labm |= (1u << j);
                    }
                }
            }
            if (labm == 3u) break;
        }
    } else {
        int cnt = s_cnt[b];
        for (int g = 0; g < cnt; ++g) {
            float4 gb = reinterpret_cast<const float4*>(gt)[b * A_ + g];
            float ga = __fmul_rn(__fsub_rn(gb.z, gb.x), __fsub_rn(gb.w, gb.y));
            float thr = __fadd_rn(area, ga);
            float kthr = thr * (1.0f / 3.0f);

            float yy1 = fminf(fmaxf(ay1, gb.x), gb.z);
            float yy2 = fminf(fmaxf(ay2, gb.x), gb.z);
            float oy  = __fsub_rn(yy2, yy1);
            float oxmax = fminf(oxm_w, __fsub_rn(gb.w, gb.y));
            if (__fmul_rn(oy, oxmax) < kthr * 0.999f) continue;

            float m_hi = kthr * 1.00002f;
            float m_lo = kthr * 0.99998f;
#pragma unroll
            for (int j = 0; j < 2; ++j) {
                float a1 = ax1_0 + (float)j * s;
                float a2 = a1 + ww;
                float xx1 = fminf(fmaxf(a1, gb.y), gb.w);
                float xx2 = fminf(fmaxf(a2, gb.y), gb.w);
                float inter = __fmul_rn(oy, __fsub_rn(xx2, xx1));
                if (inter >= m_lo) {
                    if (inter >= m_hi) labm |= (1u << j);
                    else {
                        float uni = __fsub_rn(thr, inter);
                        if (inter / uni >= 0.5f) labm |= (1u << j);
                    }
                }
            }
            if (labm == 3u) break;
        }
    }

    *reinterpret_cast<float2*>(out + OUT_LB + row) =
        make_float2((float)(labm & 1u), (float)((labm >> 1) & 1u));
}

extern "C" void kernel_launch(void* const* d_in, const int* in_sizes, int n_in,
                              void* d_out, int out_size)
{
    LvlPtrs p;
    const float* gt = nullptr;
    const int* gtc = nullptr;
    const int cs_sz[5] = {786432, 196608, 49152, 12288, 3072};
    const int bp_sz[5] = {1572864, 393216, 98304, 24576, 6144};

    for (int k = 0; k < n_in; ++k) {
        int sz = in_sizes[k];
        bool matched = false;
        for (int l = 0; l < 5 && !matched; ++l) {
            if (sz == cs_sz[l]) { p.cs[l] = (const float*)d_in[k]; matched = true; }
            else if (sz == bp_sz[l]) { p.bp[l] = (const float*)d_in[k]; matched = true; }
        }
        if (!matched) {
            if (sz == B_ * A_ * 4) gt = (const float*)d_in[k];
            else if (sz == B_)     gtc = (const int*)d_in[k];
        }
    }

    float* out = (float*)d_out;
    rpn_kernel<<<1023, 256>>>(p, gt, gtc, out);   // 1023*512 = 523776 anchors
}

// round 17
// speedup vs baseline: 1.9022x; 1.0467x over previous
#include <cuda_runtime.h>

// MaskRCNN RPN monolithic v7: v6 + split-anchor assignment (thread handles
// anchors tx and tx+256 within its 512-anchor block) so ALL stores are
// perfectly coalesced (consecutive threads -> consecutive float4/float2).

#define B_   2
#define A_   20
#define NTOT 261888

#define OUT_SC 0
#define OUT_BX (B_ * NTOT * 2)
#define OUT_AN (OUT_BX + B_ * NTOT * 4)
#define OUT_LB (OUT_AN + B_ * NTOT * 4)

struct LvlPtrs {
    const float* cs[5];
    const float* bp[5];
};

__device__ __forceinline__ void get_level(int n, int& lvl, int& offv) {
    if      (n < 196608) { lvl = 0; offv = 0;      }
    else if (n < 245760) { lvl = 1; offv = 196608; }
    else if (n < 258048) { lvl = 2; offv = 245760; }
    else if (n < 261120) { lvl = 3; offv = 258048; }
    else                 { lvl = 4; offv = 261120; }
}

__global__ void __launch_bounds__(256, 8)
rpn_kernel(LvlPtrs p,
           const float* __restrict__ gt,   // B*A*4
           const int* __restrict__ gtc,    // B (int32 as delivered)
           float* __restrict__ out)
{
    __shared__ float4 s_gb[A_];
    __shared__ float  s_sga[A_];
    __shared__ int    s_ns;
    __shared__ int    s_cnt[B_];

    int tx = threadIdx.x;
    int gid0 = blockIdx.x * 512;

    // ---- block uniformity (batch & level constant across 512 anchors?)
    int gidL = gid0 + 511;
    int bb0 = (gid0 >= NTOT) ? 1 : 0;
    int bbL = (gidL >= NTOT) ? 1 : 0;
    int lvl0, off0, lvlL, offL;
    get_level(gid0 - bb0 * NTOT, lvl0, off0);
    get_level(gidL - bbL * NTOT, lvlL, offL);
    bool uniform = (bb0 == bbL) && (lvl0 == lvlL);

    // ---- GT culling into shared (block-level)
    if (tx < B_) {
        int c = gtc[tx];
        s_cnt[tx] = (c < 0) ? 0 : (c > A_ ? A_ : c);
    }
    if (tx == 0) s_ns = 0;
    __syncthreads();

    if (uniform && tx < A_) {
        float s0    = (float)(1 << (lvl0 + 2));
        float half0 = 0.5f * (s0 - 1.0f);
        float base0 = (float)(1 << (lvl0 + 6));
        float area1 = base0 * base0;
        int log2w0  = 8 - lvl0;
        int log2hw0 = 2 * log2w0;
        int hw0     = 1 << log2hw0;
        int w0      = 1 << log2w0;

        int la0 = gid0 - bb0 * NTOT - off0;
        int laL = la0 + 511;
        int a0c = la0 >> log2hw0;
        int a1c = laL >> log2hw0;
        int yblo, ybhi;
        if (a0c != a1c) { yblo = 0; ybhi = w0 - 1; }
        else {
            yblo = (la0 & (hw0 - 1)) >> log2w0;
            ybhi = (laL & (hw0 - 1)) >> log2w0;
        }

        if (tx < s_cnt[bb0]) {
            float4 gb = reinterpret_cast<const float4*>(gt)[bb0 * A_ + tx];
            float gh = __fsub_rn(gb.z, gb.x);
            float gw = __fsub_rn(gb.w, gb.y);
            float ga = __fmul_rn(gh, gw);
            bool okA = 3.0f * fminf(area1, ga)        >= 0.999f * (area1 + ga);
            bool okB = 3.0f * fminf(2.0f * area1, ga) >= 0.999f * (2.0f * area1 + ga);
            bool survive = okA || okB;
            if (survive) {
                float lo = gb.x - base0 - half0;     // hh_max/2 = base0
                float hi = gb.z + base0 - half0;
                int gylo = (int)floorf(lo / s0) - 1;
                int gyhi = (int)ceilf (hi / s0) + 1;
                if (gyhi < yblo || gylo > ybhi) survive = false;
            }
            if (survive) {
                int slot = atomicAdd(&s_ns, 1);
                s_gb[slot]  = gb;
                s_sga[slot] = ga;
            }
        }
    }
    __syncthreads();

    int ns = s_ns;

    // ---- two anchors per thread: gid0+tx and gid0+tx+256 (coalesced stores)
#pragma unroll
    for (int j = 0; j < 2; ++j) {
        int gid = gid0 + tx + j * 256;
        int b = (gid >= NTOT) ? 1 : 0;
        int n = gid - b * NTOT;
        int lvl, offv;
        get_level(n, lvl, offv);

        int log2w  = 8 - lvl;
        int log2hw = 2 * log2w;
        int hw     = 1 << log2hw;

        int local = n - offv;
        int a   = local >> log2hw;
        int rem = local & (hw - 1);
        int y   = rem >> log2w;
        int x   = rem & ((1 << log2w) - 1);

        float s    = (float)(1 << (lvl + 2));
        float half = 0.5f * (s - 1.0f);
        float base = (float)(1 << (lvl + 6));
        float cy = s * (float)y + half;
        float cx = s * (float)x + half;
        float hh = (a == 2) ? 2.0f * base : base;
        float ww = (a == 0) ? 2.0f * base : base;

        const float* csp = p.cs[lvl];
        const float* bpp = p.bp[lvl];
        int cbase = (b * 6  + a * 2) * hw + rem;
        int bbase = (b * 12 + a * 4) * hw + rem;

        float c0 = csp[cbase];
        float c1 = csp[cbase + hw];
        float dy = bpp[bbase];
        float dx = bpp[bbase + hw];
        float dh = bpp[bbase + 2 * hw];
        float dw = bpp[bbase + 3 * hw];

        int row = b * NTOT + n;

        // stream outputs (all coalesced across the warp)
        *reinterpret_cast<float2*>(out + OUT_SC + row * 2) = make_float2(c0, c1);

        float cyc = cy + dy * hh;
        float cxc = cx + dx * ww;
        float h2  = hh * __expf(dh);
        float w2  = ww * __expf(dw);
        *reinterpret_cast<float4*>(out + OUT_BX + row * 4) =
            make_float4(cyc - 0.5f * h2, cxc - 0.5f * w2,
                        cyc + 0.5f * h2, cxc + 0.5f * w2);
        *reinterpret_cast<float4*>(out + OUT_AN + row * 4) =
            make_float4(cy, cx, hh, ww);

        // labels
        float ay1 = cy - 0.5f * hh;
        float ay2 = ay1 + hh;
        float ax1 = cx - 0.5f * ww;
        float ax2 = ax1 + ww;
        float area = __fmul_rn(hh, ww);

        float lab = 0.0f;
        if (uniform) {
            for (int k = 0; k < ns; ++k) {
                float4 gb = s_gb[k];
                float ga  = s_sga[k];
                float thr = __fadd_rn(area, ga);
                float kthr = thr * (1.0f / 3.0f);

                float yy1 = fminf(fmaxf(ay1, gb.x), gb.z);
                float yy2 = fminf(fmaxf(ay2, gb.x), gb.z);
                float oy  = __fsub_rn(yy2, yy1);
                float oxmax = fminf(ww, __fsub_rn(gb.w, gb.y));
                if (__fmul_rn(oy, oxmax) < kthr * 0.999f) continue;

                float xx1 = fminf(fmaxf(ax1, gb.y), gb.w);
                float xx2 = fminf(fmaxf(ax2, gb.y), gb.w);
                float inter = __fmul_rn(oy, __fsub_rn(xx2, xx1));
                if (inter >= kthr * 0.99998f) {
                    if (inter >= kthr * 1.00002f) { lab = 1.0f; break; }
                    float uni = __fsub_rn(thr, inter);
                    if (inter / uni >= 0.5f) { lab = 1.0f; break; }
                }
            }
        } else {
            int cnt = s_cnt[b];
            for (int g = 0; g < cnt; ++g) {
                float4 gb = reinterpret_cast<const float4*>(gt)[b * A_ + g];
                float ga = __fmul_rn(__fsub_rn(gb.z, gb.x), __fsub_rn(gb.w, gb.y));
                float thr = __fadd_rn(area, ga);
                float kthr = thr * (1.0f / 3.0f);

                float yy1 = fminf(fmaxf(ay1, gb.x), gb.z);
                float yy2 = fminf(fmaxf(ay2, gb.x), gb.z);
                float oy  = __fsub_rn(yy2, yy1);
                float oxmax = fminf(ww, __fsub_rn(gb.w, gb.y));
                if (__fmul_rn(oy, oxmax) < kthr * 0.999f) continue;

                float xx1 = fminf(fmaxf(ax1, gb.y), gb.w);
                float xx2 = fminf(fmaxf(ax2, gb.y), gb.w);
                float inter = __fmul_rn(oy, __fsub_rn(xx2, xx1));
                if (inter >= kthr * 0.99998f) {
                    if (inter >= kthr * 1.00002f) { lab = 1.0f; break; }
                    float uni = __fsub_rn(thr, inter);
                    if (inter / uni >= 0.5f) { lab = 1.0f; break; }
                }
            }
        }
        out[OUT_LB + row] = lab;
    }
}

extern "C" void kernel_launch(void* const* d_in, const int* in_sizes, int n_in,
                              void* d_out, int out_size)
{
    LvlPtrs p;
    const float* gt = nullptr;
    const int* gtc = nullptr;
    const int cs_sz[5] = {786432, 196608, 49152, 12288, 3072};
    const int bp_sz[5] = {1572864, 393216, 98304, 24576, 6144};

    for (int k = 0; k < n_in; ++k) {
        int sz = in_sizes[k];
        bool matched = false;
        for (int l = 0; l < 5 && !matched; ++l) {
            if (sz == cs_sz[l]) { p.cs[l] = (const float*)d_in[k]; matched = true; }
            else if (sz == bp_sz[l]) { p.bp[l] = (const float*)d_in[k]; matched = true; }
        }
        if (!matched) {
            if (sz == B_ * A_ * 4) gt = (const float*)d_in[k];
            else if (sz == B_)     gtc = (const int*)d_in[k];
        }
    }

    float* out = (float*)d_out;
    rpn_kernel<<<1023, 256>>>(p, gt, gtc, out);   // 1023*512 = 523776 anchors
}